// round 4
// baseline (speedup 1.0000x reference)
#include <cuda_runtime.h>
#include <cstdint>
#include <math.h>

// ---------------------------------------------------------------------------
// TopDown FPN with modulated deformable convs (DCNv2), fp32 baseline.
//   t3 = mdconv(x3)                       12x12
//   t2 = mdconv(x2 + up2(t3))             24x24
//   t1 = mdconv(x1 + up2(t2))             48x48
//   t0 = conv  (x0 + up2(t1))             96x96
// Output = concat(t0, t1, t2, t3) flattened.
//
// Per level: im2col -> SGEMM(27ch offsets, sigmoid fused on mask rows)
//            -> deformable-col gather -> SGEMM(256ch main, bias fused).
// ---------------------------------------------------------------------------

#define CIN   256
#define COUT  256
#define KK    2304   // 256*9

// Scratch (static device globals; no allocation anywhere)
__device__ float g_s[2 * 256 * 96 * 96];          // level input (x + up2(t_prev))
__device__ float g_cols[(size_t)2304 * 18432];    // col matrix, sized for level 0
__device__ float g_off[27 * 4608];                // offsets [27][N], sized for level 1

// ---------------------------------------------------------------------------
// s[b,c,h,w] = x[b,c,h,w] + tprev[b,c,h/2,w/2]
// ---------------------------------------------------------------------------
__global__ void addup_kernel(const float* __restrict__ x,
                             const float* __restrict__ tp,
                             float* __restrict__ s, int H, int W)
{
    int idx = blockIdx.x * blockDim.x + threadIdx.x;
    int HW = H * W;
    int total = 2 * CIN * HW;
    if (idx >= total) return;
    int bc = idx / HW;
    int hw = idx - bc * HW;
    int h = hw / W, w = hw - h * W;
    int Wp = W >> 1;
    int HWp = (H >> 1) * Wp;
    s[idx] = x[idx] + tp[(size_t)bc * HWp + (h >> 1) * Wp + (w >> 1)];
}

// ---------------------------------------------------------------------------
// Regular im2col for 3x3 / pad 1 conv.  cols[(ci*9+k)*N + p],  p = b*HW + hw
// ---------------------------------------------------------------------------
__global__ void im2col_kernel(const float* __restrict__ s,
                              float* __restrict__ cols,
                              int H, int W, int N)
{
    int idx = blockIdx.x * blockDim.x + threadIdx.x;
    if (idx >= CIN * N) return;
    int ci = idx / N;
    int p  = idx - ci * N;
    int HW = H * W;
    int b  = p / HW;
    int hw = p - b * HW;
    int h = hw / W, w = hw - h * W;
    const float* sp = s + ((size_t)b * CIN + ci) * HW;
    float* cb = cols + (size_t)ci * 9 * N + p;
#pragma unroll
    for (int ky = 0; ky < 3; ++ky) {
        int y = h - 1 + ky;
#pragma unroll
        for (int kx = 0; kx < 3; ++kx) {
            int x = w - 1 + kx;
            float v = 0.f;
            if ((unsigned)y < (unsigned)H && (unsigned)x < (unsigned)W)
                v = sp[y * W + x];
            cb[(size_t)(ky * 3 + kx) * N] = v;
        }
    }
}

// ---------------------------------------------------------------------------
// Deformable col build.  off is [27][N]: rows 2k=dy_k, 2k+1=dx_k, 18+k = mask
// (mask already passed through sigmoid in the offset-GEMM epilogue).
// ---------------------------------------------------------------------------
__global__ void dcols_kernel(const float* __restrict__ s,
                             const float* __restrict__ off,
                             float* __restrict__ cols,
                             int H, int W, int N)
{
    int idx = blockIdx.x * blockDim.x + threadIdx.x;
    if (idx >= CIN * N) return;
    int ci = idx / N;
    int p  = idx - ci * N;
    int HW = H * W;
    int b  = p / HW;
    int hw = p - b * HW;
    int h = hw / W, w = hw - h * W;
    const float* sp = s + ((size_t)b * CIN + ci) * HW;
    float* cb = cols + (size_t)ci * 9 * N + p;
#pragma unroll
    for (int k = 0; k < 9; ++k) {
        float dy = off[(size_t)(2 * k)     * N + p];
        float dx = off[(size_t)(2 * k + 1) * N + p];
        float m  = off[(size_t)(18 + k)    * N + p];
        float py = (float)(h - 1 + k / 3) + dy;
        float px = (float)(w - 1 + k % 3) + dx;
        float y0f = floorf(py), x0f = floorf(px);
        int   y0 = (int)y0f,   x0 = (int)x0f;
        float wy1 = py - y0f,  wx1 = px - x0f;
        float wy0 = 1.f - wy1, wx0 = 1.f - wx1;
        float v = 0.f;
        if ((unsigned)y0 < (unsigned)H) {
            const float* r0 = sp + y0 * W;
            if ((unsigned)x0       < (unsigned)W) v += r0[x0]     * (wy0 * wx0);
            if ((unsigned)(x0 + 1) < (unsigned)W) v += r0[x0 + 1] * (wy0 * wx1);
        }
        if ((unsigned)(y0 + 1) < (unsigned)H) {
            const float* r1 = sp + (y0 + 1) * W;
            if ((unsigned)x0       < (unsigned)W) v += r1[x0]     * (wy1 * wx0);
            if ((unsigned)(x0 + 1) < (unsigned)W) v += r1[x0 + 1] * (wy1 * wx1);
        }
        cb[(size_t)k * N] = v * m;
    }
}

// ---------------------------------------------------------------------------
// Tiled SGEMM: C = A[M,K] * B[K,N] + bias.
// BM=BN=128, BK=16, 256 threads, 8x8 per-thread microtile.
// sigRow >= 0: rows >= sigRow get sigmoid (offset-conv mask fusion).
// HW  >  0  : write as NCHW tensor out[(b*256+row)*HW + hw], col = b*HW+hw.
// HW == 0   : write plain C[row*N + col].
// ---------------------------------------------------------------------------
__global__ __launch_bounds__(256, 2)
void sgemm_kernel(const float* __restrict__ A, const float* __restrict__ B,
                  const float* __restrict__ bias, float* __restrict__ C,
                  int M, int N, int K, int HW, int sigRow)
{
    __shared__ __align__(16) float As[16 * 128];
    __shared__ __align__(16) float Bs[16 * 128];

    const int tid = threadIdx.x;
    const int tx = tid & 15;       // 0..15 -> N micro
    const int ty = tid >> 4;       // 0..15 -> M micro
    const int mBase = blockIdx.y * 128;
    const int nBase = blockIdx.x * 128;

    const int aK4   = tid & 3;     // float4 index along K
    const int aRowB = tid >> 2;    // 0..63
    const int bN4   = tid & 31;    // float4 index along N
    const int bKB   = tid >> 5;    // 0..7
    const int nCol  = nBase + bN4 * 4;

    float acc[8][8];
#pragma unroll
    for (int i = 0; i < 8; ++i)
#pragma unroll
        for (int j = 0; j < 8; ++j) acc[i][j] = 0.f;

    const int KT = K >> 4;
    for (int kt = 0; kt < KT; ++kt) {
        // load A tile (transposed into As[k][m])
#pragma unroll
        for (int it = 0; it < 2; ++it) {
            int aRow = aRowB + it * 64;
            int gRow = mBase + aRow;
            float4 v = make_float4(0.f, 0.f, 0.f, 0.f);
            if (gRow < M)
                v = *(const float4*)(A + (size_t)gRow * K + (kt << 4) + (aK4 << 2));
            As[(aK4 * 4 + 0) * 128 + aRow] = v.x;
            As[(aK4 * 4 + 1) * 128 + aRow] = v.y;
            As[(aK4 * 4 + 2) * 128 + aRow] = v.z;
            As[(aK4 * 4 + 3) * 128 + aRow] = v.w;
        }
        // load B tile
#pragma unroll
        for (int it = 0; it < 2; ++it) {
            int bK = bKB + it * 8;
            float4 v = make_float4(0.f, 0.f, 0.f, 0.f);
            if (nCol < N)
                v = *(const float4*)(B + (size_t)((kt << 4) + bK) * N + nCol);
            *(float4*)&Bs[bK * 128 + bN4 * 4] = v;
        }
        __syncthreads();

#pragma unroll
        for (int k = 0; k < 16; ++k) {
            float a[8], b[8];
            *(float4*)&a[0] = *(const float4*)&As[k * 128 + ty * 8];
            *(float4*)&a[4] = *(const float4*)&As[k * 128 + ty * 8 + 4];
            *(float4*)&b[0] = *(const float4*)&Bs[k * 128 + tx * 8];
            *(float4*)&b[4] = *(const float4*)&Bs[k * 128 + tx * 8 + 4];
#pragma unroll
            for (int i = 0; i < 8; ++i)
#pragma unroll
                for (int j = 0; j < 8; ++j)
                    acc[i][j] += a[i] * b[j];
        }
        __syncthreads();
    }

    // epilogue
#pragma unroll
    for (int i = 0; i < 8; ++i) {
        int row = mBase + ty * 8 + i;
        if (row >= M) continue;
        float bv = bias[row];
#pragma unroll
        for (int j = 0; j < 8; ++j) {
            int col = nBase + tx * 8 + j;
            if (col >= N) continue;
            float v = acc[i][j] + bv;
            if (sigRow >= 0 && row >= sigRow)
                v = 1.f / (1.f + expf(-v));
            if (HW > 0) {
                int bb = col / HW;
                int hw = col - bb * HW;
                C[((size_t)bb * COUT + row) * HW + hw] = v;
            } else {
                C[(size_t)row * N + col] = v;
            }
        }
    }
}

// ---------------------------------------------------------------------------
// Host side
// ---------------------------------------------------------------------------
static inline dim3 gemm_grid(int M, int N)
{
    return dim3((N + 127) / 128, (M + 127) / 128);
}

extern "C" void kernel_launch(void* const* d_in, const int* in_sizes, int n_in,
                              void* d_out, int out_size)
{
    // Classify inputs by element count (robust to dict- vs signature-order).
    const float* xs[4]  = {nullptr, nullptr, nullptr, nullptr};
    const float* ws[4]  = {nullptr, nullptr, nullptr, nullptr};
    const float* bs[4]  = {nullptr, nullptr, nullptr, nullptr};
    const float* ows[3] = {nullptr, nullptr, nullptr};  // ow1, ow2, ow3
    const float* obs[3] = {nullptr, nullptr, nullptr};  // ob1, ob2, ob3
    int wi = 0, bi = 0, owi = 0, obi = 0;
    for (int i = 0; i < n_in; ++i) {
        const float* p = (const float*)d_in[i];
        switch (in_sizes[i]) {
            case 2 * 256 * 96 * 96: xs[0] = p; break;
            case 2 * 256 * 48 * 48: xs[1] = p; break;
            case 2 * 256 * 24 * 24: xs[2] = p; break;
            case 2 * 256 * 12 * 12: xs[3] = p; break;
            case 256 * 256 * 3 * 3: if (wi  < 4) ws[wi++]   = p; break;
            case 256:               if (bi  < 4) bs[bi++]   = p; break;
            case 27 * 256 * 3 * 3:  if (owi < 3) ows[owi++] = p; break;
            case 27:                if (obi < 3) obs[obi++] = p; break;
            default: break;
        }
    }

    float* out = (float*)d_out;
    float* s;    cudaGetSymbolAddress((void**)&s,    g_s);
    float* cols; cudaGetSymbolAddress((void**)&cols, g_cols);
    float* off;  cudaGetSymbolAddress((void**)&off,  g_off);

    // output slots: t0, t1, t2, t3
    const size_t OFF0 = 0;
    const size_t OFF1 = OFF0 + (size_t)2 * 256 * 96 * 96;
    const size_t OFF2 = OFF1 + (size_t)2 * 256 * 48 * 48;
    const size_t OFF3 = OFF2 + (size_t)2 * 256 * 24 * 24;
    const size_t outOff[4] = {OFF0, OFF1, OFF2, OFF3};

    const int Hs[4] = {96, 48, 24, 12};

    // ---- levels 3, 2, 1: modulated deformable conv ----
    for (int lvl = 3; lvl >= 1; --lvl) {
        int H = Hs[lvl], W = H;
        int HW = H * W;
        int N = 2 * HW;

        const float* sin;
        if (lvl == 3) {
            sin = xs[3];
        } else {
            int total = 2 * CIN * HW;
            addup_kernel<<<(total + 255) / 256, 256>>>(
                xs[lvl], out + outOff[lvl + 1], s, H, W);
            sin = s;
        }

        // regular im2col for the offset conv
        im2col_kernel<<<(CIN * N + 255) / 256, 256>>>(sin, cols, H, W, N);

        // offset conv: M=27, sigmoid fused on mask rows [18..26]
        sgemm_kernel<<<gemm_grid(27, N), 256>>>(
            ows[lvl - 1], cols, obs[lvl - 1], off, 27, N, KK, 0, 18);

        // deformable col matrix
        dcols_kernel<<<(CIN * N + 255) / 256, 256>>>(sin, off, cols, H, W, N);

        // main conv: M=256, write NCHW into the output slot
        sgemm_kernel<<<gemm_grid(COUT, N), 256>>>(
            ws[lvl], cols, bs[lvl], out + outOff[lvl], COUT, N, KK, HW, -1);
    }

    // ---- level 0: plain conv on x0 + up2(t1) ----
    {
        int H = 96, W = 96, HW = H * W, N = 2 * HW;
        int total = 2 * CIN * HW;
        addup_kernel<<<(total + 255) / 256, 256>>>(xs[0], out + OFF1, s, H, W);
        im2col_kernel<<<(CIN * N + 255) / 256, 256>>>(s, cols, H, W, N);
        sgemm_kernel<<<gemm_grid(COUT, N), 256>>>(
            ws[0], cols, bs[0], out + OFF0, COUT, N, KK, HW, -1);
    }
}

// round 5
// speedup vs baseline: 1.5241x; 1.5241x over previous
#include <cuda_runtime.h>
#include <cstdint>
#include <math.h>

// ---------------------------------------------------------------------------
// TopDown FPN with modulated deformable convs (DCNv2), fp32, split-K GEMMs.
//   t3 = mdconv(x3)                       12x12
//   t2 = mdconv(x2 + up2(t3))             24x24
//   t1 = mdconv(x1 + up2(t2))             48x48
//   t0 = conv  (x0 + up2(t1))             96x96
// Output = concat(t0, t1, t2, t3) flattened.
//
// Small-N GEMMs use split-K (partials + deterministic reduce) so every launch
// fills the chip (~216-288 CTAs). Level-0 main GEMM (288 CTAs) stays fused.
// ---------------------------------------------------------------------------

#define CIN   256
#define COUT  256
#define KK    2304   // 256*9

// Scratch (static device globals; no allocation anywhere)
__device__ float g_s[2 * 256 * 96 * 96];          // level input (x + up2(t_prev))
__device__ float g_cols[(size_t)2304 * 18432];    // col matrix, sized for level 0
__device__ float g_off[27 * 4608];                // offsets [27][N], sized for level 1
__device__ float g_part[5 * 1024 * 1024];         // split-K partials (max 4.72M floats)

// ---------------------------------------------------------------------------
// s[b,c,h,w] = x[b,c,h,w] + tprev[b,c,h/2,w/2]
// ---------------------------------------------------------------------------
__global__ void addup_kernel(const float* __restrict__ x,
                             const float* __restrict__ tp,
                             float* __restrict__ s, int H, int W)
{
    int idx = blockIdx.x * blockDim.x + threadIdx.x;
    int HW = H * W;
    int total = 2 * CIN * HW;
    if (idx >= total) return;
    int bc = idx / HW;
    int hw = idx - bc * HW;
    int h = hw / W, w = hw - h * W;
    int Wp = W >> 1;
    int HWp = (H >> 1) * Wp;
    s[idx] = x[idx] + tp[(size_t)bc * HWp + (h >> 1) * Wp + (w >> 1)];
}

// ---------------------------------------------------------------------------
// Regular im2col for 3x3 / pad 1 conv.  cols[(ci*9+k)*N + p],  p = b*HW + hw
// ---------------------------------------------------------------------------
__global__ void im2col_kernel(const float* __restrict__ s,
                              float* __restrict__ cols,
                              int H, int W, int N)
{
    int idx = blockIdx.x * blockDim.x + threadIdx.x;
    if (idx >= CIN * N) return;
    int ci = idx / N;
    int p  = idx - ci * N;
    int HW = H * W;
    int b  = p / HW;
    int hw = p - b * HW;
    int h = hw / W, w = hw - h * W;
    const float* sp = s + ((size_t)b * CIN + ci) * HW;
    float* cb = cols + (size_t)ci * 9 * N + p;
#pragma unroll
    for (int ky = 0; ky < 3; ++ky) {
        int y = h - 1 + ky;
#pragma unroll
        for (int kx = 0; kx < 3; ++kx) {
            int x = w - 1 + kx;
            float v = 0.f;
            if ((unsigned)y < (unsigned)H && (unsigned)x < (unsigned)W)
                v = sp[y * W + x];
            cb[(size_t)(ky * 3 + kx) * N] = v;
        }
    }
}

// ---------------------------------------------------------------------------
// Deformable col build.  off is [27][N]: rows 2k=dy_k, 2k+1=dx_k, 18+k = mask
// (mask already sigmoided by the reduce kernel).
// ---------------------------------------------------------------------------
__global__ void dcols_kernel(const float* __restrict__ s,
                             const float* __restrict__ off,
                             float* __restrict__ cols,
                             int H, int W, int N)
{
    int idx = blockIdx.x * blockDim.x + threadIdx.x;
    if (idx >= CIN * N) return;
    int ci = idx / N;
    int p  = idx - ci * N;
    int HW = H * W;
    int b  = p / HW;
    int hw = p - b * HW;
    int h = hw / W, w = hw - h * W;
    const float* sp = s + ((size_t)b * CIN + ci) * HW;
    float* cb = cols + (size_t)ci * 9 * N + p;
#pragma unroll
    for (int k = 0; k < 9; ++k) {
        float dy = off[(size_t)(2 * k)     * N + p];
        float dx = off[(size_t)(2 * k + 1) * N + p];
        float m  = off[(size_t)(18 + k)    * N + p];
        float py = (float)(h - 1 + k / 3) + dy;
        float px = (float)(w - 1 + k % 3) + dx;
        float y0f = floorf(py), x0f = floorf(px);
        int   y0 = (int)y0f,   x0 = (int)x0f;
        float wy1 = py - y0f,  wx1 = px - x0f;
        float wy0 = 1.f - wy1, wx0 = 1.f - wx1;
        float v = 0.f;
        if ((unsigned)y0 < (unsigned)H) {
            const float* r0 = sp + y0 * W;
            if ((unsigned)x0       < (unsigned)W) v += r0[x0]     * (wy0 * wx0);
            if ((unsigned)(x0 + 1) < (unsigned)W) v += r0[x0 + 1] * (wy0 * wx1);
        }
        if ((unsigned)(y0 + 1) < (unsigned)H) {
            const float* r1 = sp + (y0 + 1) * W;
            if ((unsigned)x0       < (unsigned)W) v += r1[x0]     * (wy1 * wx0);
            if ((unsigned)(x0 + 1) < (unsigned)W) v += r1[x0 + 1] * (wy1 * wx1);
        }
        cb[(size_t)k * N] = v * m;
    }
}

// ---------------------------------------------------------------------------
// Fused SGEMM (full K): C = A[M,K]*B[K,N] + bias, NCHW epilogue.
// BM=BN=128, BK=16, 256 threads, 8x8 microtile. Used for level-0 main conv.
// ---------------------------------------------------------------------------
__global__ __launch_bounds__(256, 2)
void sgemm_kernel(const float* __restrict__ A, const float* __restrict__ B,
                  const float* __restrict__ bias, float* __restrict__ C,
                  int M, int N, int K, int HW)
{
    __shared__ __align__(16) float As[16 * 128];
    __shared__ __align__(16) float Bs[16 * 128];

    const int tid = threadIdx.x;
    const int tx = tid & 15;
    const int ty = tid >> 4;
    const int mBase = blockIdx.y * 128;
    const int nBase = blockIdx.x * 128;

    const int aK4   = tid & 3;
    const int aRowB = tid >> 2;
    const int bN4   = tid & 31;
    const int bKB   = tid >> 5;
    const int nCol  = nBase + bN4 * 4;

    float acc[8][8];
#pragma unroll
    for (int i = 0; i < 8; ++i)
#pragma unroll
        for (int j = 0; j < 8; ++j) acc[i][j] = 0.f;

    const int KT = K >> 4;
    for (int kt = 0; kt < KT; ++kt) {
#pragma unroll
        for (int it = 0; it < 2; ++it) {
            int aRow = aRowB + it * 64;
            int gRow = mBase + aRow;
            float4 v = make_float4(0.f, 0.f, 0.f, 0.f);
            if (gRow < M)
                v = *(const float4*)(A + (size_t)gRow * K + (kt << 4) + (aK4 << 2));
            As[(aK4 * 4 + 0) * 128 + aRow] = v.x;
            As[(aK4 * 4 + 1) * 128 + aRow] = v.y;
            As[(aK4 * 4 + 2) * 128 + aRow] = v.z;
            As[(aK4 * 4 + 3) * 128 + aRow] = v.w;
        }
#pragma unroll
        for (int it = 0; it < 2; ++it) {
            int bK = bKB + it * 8;
            float4 v = make_float4(0.f, 0.f, 0.f, 0.f);
            if (nCol < N)
                v = *(const float4*)(B + (size_t)((kt << 4) + bK) * N + nCol);
            *(float4*)&Bs[bK * 128 + bN4 * 4] = v;
        }
        __syncthreads();

#pragma unroll
        for (int k = 0; k < 16; ++k) {
            float a[8], b[8];
            *(float4*)&a[0] = *(const float4*)&As[k * 128 + ty * 8];
            *(float4*)&a[4] = *(const float4*)&As[k * 128 + ty * 8 + 4];
            *(float4*)&b[0] = *(const float4*)&Bs[k * 128 + tx * 8];
            *(float4*)&b[4] = *(const float4*)&Bs[k * 128 + tx * 8 + 4];
#pragma unroll
            for (int i = 0; i < 8; ++i)
#pragma unroll
                for (int j = 0; j < 8; ++j)
                    acc[i][j] += a[i] * b[j];
        }
        __syncthreads();
    }

#pragma unroll
    for (int i = 0; i < 8; ++i) {
        int row = mBase + ty * 8 + i;
        if (row >= M) continue;
        float bv = bias[row];
#pragma unroll
        for (int j = 0; j < 8; ++j) {
            int col = nBase + tx * 8 + j;
            if (col >= N) continue;
            float v = acc[i][j] + bv;
            int bb = col / HW;
            int hw = col - bb * HW;
            C[((size_t)bb * COUT + row) * HW + hw] = v;
        }
    }
}

// ---------------------------------------------------------------------------
// Split-K partial SGEMM: P[z][M][N] = A[M, kStart:kStart+kLen] * B[.., N]
// Same tiling as sgemm_kernel; blockIdx.z selects the K chunk.
// ---------------------------------------------------------------------------
__global__ __launch_bounds__(256, 2)
void sgemm_part_kernel(const float* __restrict__ A, const float* __restrict__ B,
                       float* __restrict__ P, int M, int N, int K, int kLen)
{
    __shared__ __align__(16) float As[16 * 128];
    __shared__ __align__(16) float Bs[16 * 128];

    const int tid = threadIdx.x;
    const int tx = tid & 15;
    const int ty = tid >> 4;
    const int mBase = blockIdx.y * 128;
    const int nBase = blockIdx.x * 128;
    const int kStart = blockIdx.z * kLen;

    const int aK4   = tid & 3;
    const int aRowB = tid >> 2;
    const int bN4   = tid & 31;
    const int bKB   = tid >> 5;
    const int nCol  = nBase + bN4 * 4;

    float acc[8][8];
#pragma unroll
    for (int i = 0; i < 8; ++i)
#pragma unroll
        for (int j = 0; j < 8; ++j) acc[i][j] = 0.f;

    const int KT = kLen >> 4;
    for (int kt = 0; kt < KT; ++kt) {
        const int kOff = kStart + (kt << 4);
#pragma unroll
        for (int it = 0; it < 2; ++it) {
            int aRow = aRowB + it * 64;
            int gRow = mBase + aRow;
            float4 v = make_float4(0.f, 0.f, 0.f, 0.f);
            if (gRow < M)
                v = *(const float4*)(A + (size_t)gRow * K + kOff + (aK4 << 2));
            As[(aK4 * 4 + 0) * 128 + aRow] = v.x;
            As[(aK4 * 4 + 1) * 128 + aRow] = v.y;
            As[(aK4 * 4 + 2) * 128 + aRow] = v.z;
            As[(aK4 * 4 + 3) * 128 + aRow] = v.w;
        }
#pragma unroll
        for (int it = 0; it < 2; ++it) {
            int bK = bKB + it * 8;
            float4 v = make_float4(0.f, 0.f, 0.f, 0.f);
            if (nCol < N)
                v = *(const float4*)(B + (size_t)(kOff + bK) * N + nCol);
            *(float4*)&Bs[bK * 128 + bN4 * 4] = v;
        }
        __syncthreads();

#pragma unroll
        for (int k = 0; k < 16; ++k) {
            float a[8], b[8];
            *(float4*)&a[0] = *(const float4*)&As[k * 128 + ty * 8];
            *(float4*)&a[4] = *(const float4*)&As[k * 128 + ty * 8 + 4];
            *(float4*)&b[0] = *(const float4*)&Bs[k * 128 + tx * 8];
            *(float4*)&b[4] = *(const float4*)&Bs[k * 128 + tx * 8 + 4];
#pragma unroll
            for (int i = 0; i < 8; ++i)
#pragma unroll
                for (int j = 0; j < 8; ++j)
                    acc[i][j] += a[i] * b[j];
        }
        __syncthreads();
    }

    float* Pb = P + (size_t)blockIdx.z * M * N;
#pragma unroll
    for (int i = 0; i < 8; ++i) {
        int row = mBase + ty * 8 + i;
        if (row >= M) continue;
#pragma unroll
        for (int j = 0; j < 8; ++j) {
            int col = nBase + tx * 8 + j;
            if (col >= N) continue;
            Pb[(size_t)row * N + col] = acc[i][j];
        }
    }
}

// ---------------------------------------------------------------------------
// Reduce split-K partials for the offset conv: 27 rows, +bias, sigmoid on
// mask rows [18..26]. off[27][N].
// ---------------------------------------------------------------------------
__global__ void reduce_off_kernel(const float* __restrict__ P,
                                  const float* __restrict__ ob,
                                  float* __restrict__ off, int N, int S)
{
    int idx = blockIdx.x * blockDim.x + threadIdx.x;
    if (idx >= 27 * N) return;
    int r = idx / N;
    float v = ob[r];
    for (int s = 0; s < S; ++s)
        v += P[(size_t)s * 27 * N + idx];
    if (r >= 18)
        v = 1.f / (1.f + expf(-v));
    off[idx] = v;
}

// ---------------------------------------------------------------------------
// Reduce split-K partials for the main conv: 256 rows, +bias, NCHW write.
// ---------------------------------------------------------------------------
__global__ void reduce_main_kernel(const float* __restrict__ P,
                                   const float* __restrict__ bias,
                                   float* __restrict__ out, int N, int HW, int S)
{
    int idx = blockIdx.x * blockDim.x + threadIdx.x;
    if (idx >= COUT * N) return;
    int row = idx / N;
    int col = idx - row * N;
    float v = bias[row];
    for (int s = 0; s < S; ++s)
        v += P[(size_t)s * COUT * N + idx];
    int bb = col / HW;
    int hw = col - bb * HW;
    out[((size_t)bb * COUT + row) * HW + hw] = v;
}

// ---------------------------------------------------------------------------
// Host side
// ---------------------------------------------------------------------------
extern "C" void kernel_launch(void* const* d_in, const int* in_sizes, int n_in,
                              void* d_out, int out_size)
{
    const float* xs[4]  = {nullptr, nullptr, nullptr, nullptr};
    const float* ws[4]  = {nullptr, nullptr, nullptr, nullptr};
    const float* bs[4]  = {nullptr, nullptr, nullptr, nullptr};
    const float* ows[3] = {nullptr, nullptr, nullptr};
    const float* obs[3] = {nullptr, nullptr, nullptr};
    int wi = 0, bi = 0, owi = 0, obi = 0;
    for (int i = 0; i < n_in; ++i) {
        const float* p = (const float*)d_in[i];
        switch (in_sizes[i]) {
            case 2 * 256 * 96 * 96: xs[0] = p; break;
            case 2 * 256 * 48 * 48: xs[1] = p; break;
            case 2 * 256 * 24 * 24: xs[2] = p; break;
            case 2 * 256 * 12 * 12: xs[3] = p; break;
            case 256 * 256 * 3 * 3: if (wi  < 4) ws[wi++]   = p; break;
            case 256:               if (bi  < 4) bs[bi++]   = p; break;
            case 27 * 256 * 3 * 3:  if (owi < 3) ows[owi++] = p; break;
            case 27:                if (obi < 3) obs[obi++] = p; break;
            default: break;
        }
    }

    float* out = (float*)d_out;
    float* s;    cudaGetSymbolAddress((void**)&s,    g_s);
    float* cols; cudaGetSymbolAddress((void**)&cols, g_cols);
    float* off;  cudaGetSymbolAddress((void**)&off,  g_off);
    float* part; cudaGetSymbolAddress((void**)&part, g_part);

    const size_t OFF0 = 0;
    const size_t OFF1 = OFF0 + (size_t)2 * 256 * 96 * 96;
    const size_t OFF2 = OFF1 + (size_t)2 * 256 * 48 * 48;
    const size_t OFF3 = OFF2 + (size_t)2 * 256 * 24 * 24;
    const size_t outOff[4] = {OFF0, OFF1, OFF2, OFF3};

    const int Hs[4]    = {96, 48, 24, 12};
    // split-K factors per level (index by lvl); K chunk = 2304/S, multiple of 16
    const int mainS[4] = {1, 4, 12, 36};
    const int offS[4]  = {1, 8, 24, 72};

    // ---- levels 3, 2, 1: modulated deformable conv ----
    for (int lvl = 3; lvl >= 1; --lvl) {
        int H = Hs[lvl], W = H;
        int HW = H * W;
        int N = 2 * HW;

        const float* sin;
        if (lvl == 3) {
            sin = xs[3];
        } else {
            int total = 2 * CIN * HW;
            addup_kernel<<<(total + 255) / 256, 256>>>(
                xs[lvl], out + outOff[lvl + 1], s, H, W);
            sin = s;
        }

        im2col_kernel<<<(CIN * N + 255) / 256, 256>>>(sin, cols, H, W, N);

        // offset conv (M=27) via split-K
        {
            int S = offS[lvl];
            dim3 grid((N + 127) / 128, 1, S);
            sgemm_part_kernel<<<grid, 256>>>(ows[lvl - 1], cols, part,
                                             27, N, KK, KK / S);
            reduce_off_kernel<<<(27 * N + 255) / 256, 256>>>(
                part, obs[lvl - 1], off, N, S);
        }

        dcols_kernel<<<(CIN * N + 255) / 256, 256>>>(sin, off, cols, H, W, N);

        // main conv (M=256) via split-K, NCHW write in reduce
        {
            int S = mainS[lvl];
            dim3 grid((N + 127) / 128, 2, S);
            sgemm_part_kernel<<<grid, 256>>>(ws[lvl], cols, part,
                                             COUT, N, KK, KK / S);
            reduce_main_kernel<<<(COUT * N + 255) / 256, 256>>>(
                part, bs[lvl], out + outOff[lvl], N, HW, S);
        }
    }

    // ---- level 0: plain conv on x0 + up2(t1), fused GEMM (288 CTAs) ----
    {
        int H = 96, W = 96, HW = H * W, N = 2 * HW;
        int total = 2 * CIN * HW;
        addup_kernel<<<(total + 255) / 256, 256>>>(xs[0], out + OFF1, s, H, W);
        im2col_kernel<<<(CIN * N + 255) / 256, 256>>>(s, cols, H, W, N);
        dim3 grid((N + 127) / 128, 2);
        sgemm_kernel<<<grid, 256>>>(ws[0], cols, bs[0], out + OFF0,
                                    COUT, N, KK, HW);
    }
}

// round 9
// speedup vs baseline: 4.4955x; 2.9496x over previous
#include <cuda_runtime.h>
#include <cuda_bf16.h>
#include <cstdint>
#include <math.h>

// ---------------------------------------------------------------------------
// TopDown FPN (DCNv2 levels 3..1 + plain conv level 0).
// GEMMs on tensor cores via mma.sync bf16 (sm_80+ ISA, valid on base sm_103)
// with fp32 accumulation and a hi/lo bf16 split:
//     C = Ahi*Bhi + Ahi*Blo + Alo*Bhi      (a = ahi + alo)
// A (weights) is [M][K] bf16 hi/lo; B (cols) is [K][N] bf16 hi/lo, built
// directly by im2col/dcols. Small levels use split-K + deterministic reduce.
// R8 fix: B-fragment smem offset was warpN*128B (64 cols) instead of
// warpN*64B (32 cols) -> wrong data + smem OOB (the illegal access).
// ---------------------------------------------------------------------------

#define CIN   256
#define COUT  256
#define KK    2304      // 256*9
#define KT    72        // K iterations of BK=32

// smem per buffer: Ahi[128][40] Alo[128][40] Bhi[32][136] Blo[32][136]
#define A_TILE_B   10240      // 128*40*2
#define B_TILE_B   8704       // 32*136*2
#define BUF_B      37888      // 2*A_TILE_B + 2*B_TILE_B
#define GEMM_SMEM  (2 * BUF_B)

// ---- scratch (static device globals; no allocation anywhere) --------------
__device__ float g_s[2 * 256 * 96 * 96];
__device__ float g_off[27 * 4608];
__device__ float g_part[5 * 1024 * 1024];
__device__ __align__(16) __nv_bfloat16 g_colshi[(size_t)2304 * 18432];
__device__ __align__(16) __nv_bfloat16 g_colslo[(size_t)2304 * 18432];
__device__ __align__(16) __nv_bfloat16 g_whi[4][256 * 2304];
__device__ __align__(16) __nv_bfloat16 g_wlo[4][256 * 2304];
__device__ __align__(16) __nv_bfloat16 g_owhi[3][27 * 2304];
__device__ __align__(16) __nv_bfloat16 g_owlo[3][27 * 2304];

// ---------------------------------------------------------------------------
// PTX helpers (sm_80-era, valid on base sm_103 target)
// ---------------------------------------------------------------------------
__device__ __forceinline__ uint32_t smem_u32(const void* p) {
    uint32_t a;
    asm("{ .reg .u64 t; cvta.to.shared.u64 t, %1; cvt.u32.u64 %0, t; }"
        : "=r"(a) : "l"(p));
    return a;
}
__device__ __forceinline__ void cp16(uint32_t dst, const void* src, bool ok) {
    int sz = ok ? 16 : 0;
    asm volatile("cp.async.ca.shared.global [%0], [%1], 16, %2;"
                 :: "r"(dst), "l"(src), "r"(sz) : "memory");
}
#define CP_COMMIT() asm volatile("cp.async.commit_group;" ::: "memory")
#define CP_WAIT1()  asm volatile("cp.async.wait_group 1;"  ::: "memory")

__device__ __forceinline__ void ldsm_x4(uint32_t* r, uint32_t a) {
    asm volatile("ldmatrix.sync.aligned.m8n8.x4.shared.b16 {%0,%1,%2,%3}, [%4];"
                 : "=r"(r[0]), "=r"(r[1]), "=r"(r[2]), "=r"(r[3]) : "r"(a));
}
__device__ __forceinline__ void ldsm_x2t(uint32_t* r, uint32_t a) {
    asm volatile("ldmatrix.sync.aligned.m8n8.x2.trans.shared.b16 {%0,%1}, [%2];"
                 : "=r"(r[0]), "=r"(r[1]) : "r"(a));
}
__device__ __forceinline__ void mma16816(float* d, const uint32_t* a,
                                         const uint32_t* b) {
    asm volatile(
        "mma.sync.aligned.m16n8k16.row.col.f32.bf16.bf16.f32 "
        "{%0,%1,%2,%3}, {%4,%5,%6,%7}, {%8,%9}, {%0,%1,%2,%3};"
        : "+f"(d[0]), "+f"(d[1]), "+f"(d[2]), "+f"(d[3])
        : "r"(a[0]), "r"(a[1]), "r"(a[2]), "r"(a[3]), "r"(b[0]), "r"(b[1]));
}

// ---------------------------------------------------------------------------
// glue kernels
// ---------------------------------------------------------------------------
__global__ void addup_kernel(const float* __restrict__ x,
                             const float* __restrict__ tp,
                             float* __restrict__ s, int H, int W)
{
    int idx = blockIdx.x * blockDim.x + threadIdx.x;
    int HW = H * W;
    int total = 2 * CIN * HW;
    if (idx >= total) return;
    int bc = idx / HW;
    int hw = idx - bc * HW;
    int h = hw / W, w = hw - h * W;
    int Wp = W >> 1;
    int HWp = (H >> 1) * Wp;
    s[idx] = x[idx] + tp[(size_t)bc * HWp + (h >> 1) * Wp + (w >> 1)];
}

__device__ __forceinline__ void split_store(__nv_bfloat16* hi,
                                            __nv_bfloat16* lo,
                                            size_t o, float v)
{
    __nv_bfloat16 h = __float2bfloat16(v);
    hi[o] = h;
    lo[o] = __float2bfloat16(v - __bfloat162float(h));
}

// im2col -> bf16 hi/lo, layout [(ci*9+k)][N], p = b*HW + hw contiguous
__global__ void im2col_kernel(const float* __restrict__ s,
                              __nv_bfloat16* __restrict__ hi,
                              __nv_bfloat16* __restrict__ lo,
                              int H, int W, int N)
{
    int idx = blockIdx.x * blockDim.x + threadIdx.x;
    if (idx >= CIN * N) return;
    int ci = idx / N;
    int p  = idx - ci * N;
    int HW = H * W;
    int b  = p / HW;
    int hw = p - b * HW;
    int h = hw / W, w = hw - h * W;
    const float* sp = s + ((size_t)b * CIN + ci) * HW;
    size_t base = (size_t)ci * 9 * N + p;
#pragma unroll
    for (int ky = 0; ky < 3; ++ky) {
        int y = h - 1 + ky;
#pragma unroll
        for (int kx = 0; kx < 3; ++kx) {
            int x = w - 1 + kx;
            float v = 0.f;
            if ((unsigned)y < (unsigned)H && (unsigned)x < (unsigned)W)
                v = sp[y * W + x];
            split_store(hi, lo, base + (size_t)(ky * 3 + kx) * N, v);
        }
    }
}

// deformable cols -> bf16 hi/lo, same layout
__global__ void dcols_kernel(const float* __restrict__ s,
                             const float* __restrict__ off,
                             __nv_bfloat16* __restrict__ hi,
                             __nv_bfloat16* __restrict__ lo,
                             int H, int W, int N)
{
    int idx = blockIdx.x * blockDim.x + threadIdx.x;
    if (idx >= CIN * N) return;
    int ci = idx / N;
    int p  = idx - ci * N;
    int HW = H * W;
    int b  = p / HW;
    int hw = p - b * HW;
    int h = hw / W, w = hw - h * W;
    const float* sp = s + ((size_t)b * CIN + ci) * HW;
    size_t base = (size_t)ci * 9 * N + p;
#pragma unroll
    for (int k = 0; k < 9; ++k) {
        float dy = off[(size_t)(2 * k)     * N + p];
        float dx = off[(size_t)(2 * k + 1) * N + p];
        float m  = off[(size_t)(18 + k)    * N + p];
        float py = (float)(h - 1 + k / 3) + dy;
        float px = (float)(w - 1 + k % 3) + dx;
        float y0f = floorf(py), x0f = floorf(px);
        int   y0 = (int)y0f,   x0 = (int)x0f;
        float wy1 = py - y0f,  wx1 = px - x0f;
        float wy0 = 1.f - wy1, wx0 = 1.f - wx1;
        float v = 0.f;
        if ((unsigned)y0 < (unsigned)H) {
            const float* r0 = sp + y0 * W;
            if ((unsigned)x0       < (unsigned)W) v += r0[x0]     * (wy0 * wx0);
            if ((unsigned)(x0 + 1) < (unsigned)W) v += r0[x0 + 1] * (wy0 * wx1);
        }
        if ((unsigned)(y0 + 1) < (unsigned)H) {
            const float* r1 = sp + (y0 + 1) * W;
            if ((unsigned)x0       < (unsigned)W) v += r1[x0]     * (wy1 * wx0);
            if ((unsigned)(x0 + 1) < (unsigned)W) v += r1[x0 + 1] * (wy1 * wx1);
        }
        split_store(hi, lo, base + (size_t)k * N, v * m);
    }
}

// fp32 -> bf16 hi/lo elementwise (weights, [M][K] row-major preserved)
__global__ void wsplit_kernel(const float* __restrict__ w,
                              __nv_bfloat16* __restrict__ hi,
                              __nv_bfloat16* __restrict__ lo, int n)
{
    int i = blockIdx.x * blockDim.x + threadIdx.x;
    if (i >= n) return;
    float v = w[i];
    __nv_bfloat16 h = __float2bfloat16(v);
    hi[i] = h;
    lo[i] = __float2bfloat16(v - __bfloat162float(h));
}

// ---------------------------------------------------------------------------
// Tensor-core GEMM: per CTA 128x128, BK=32, 8 warps (2m x 4n, warp 64x32),
// mma.m16n8k16 bf16, cp.async double buffering.
// A: [M][2304] hi/lo (row-major). B: [2304][Ntot] hi/lo (N contiguous).
// S==1: fused bias + NCHW epilogue.  S>1: fp32 partials at C + z*M*Ntot.
// ---------------------------------------------------------------------------
__global__ __launch_bounds__(256)
void gemm_kernel(const __nv_bfloat16* __restrict__ Ahi,
                 const __nv_bfloat16* __restrict__ Alo,
                 const __nv_bfloat16* __restrict__ Bhi,
                 const __nv_bfloat16* __restrict__ Blo,
                 const float* __restrict__ bias,
                 float* __restrict__ C,
                 int M, int Ntot, int HW, int S)
{
    extern __shared__ __align__(16) char smem[];
    const uint32_t sb = smem_u32(smem);
    const int tid  = threadIdx.x;
    const int lane = tid & 31;
    const int wid  = tid >> 5;
    const int warpM = wid & 1;
    const int warpN = wid >> 1;
    const int mBase = blockIdx.y << 7;
    const int nBase = blockIdx.x << 7;
    const int iters  = KT / S;
    const int kStart = blockIdx.z * iters * 32;

    float acc[4][4][4];
#pragma unroll
    for (int mi = 0; mi < 4; ++mi)
#pragma unroll
        for (int ni = 0; ni < 4; ++ni)
#pragma unroll
            for (int q = 0; q < 4; ++q) acc[mi][ni][q] = 0.f;

    // ---- tile loader (cp.async): 2048 x 16B chunks per buffer ----
    auto load_tiles = [&](int buf, int it) {
        const int kb = kStart + it * 32;
        const uint32_t base = sb + buf * BUF_B;
#pragma unroll
        for (int p = 0; p < 8; ++p) {
            const int u = tid + (p << 8);
            if (u < 1024) {                 // A tiles: 128 rows x 4 chunks
                const __nv_bfloat16* srcb = (u < 512) ? Ahi : Alo;
                const int v = u & 511;
                const int row = v >> 2, c = v & 3;
                const int gr = mBase + row;
                const bool ok = gr < M;
                const void* src = srcb + (size_t)(ok ? gr : 0) * KK + kb + c * 8;
                uint32_t dst = base + ((u < 512) ? 0 : A_TILE_B)
                             + row * 80 + c * 16;
                cp16(dst, src, ok);
            } else {                        // B tiles: 32 k-rows x 16 chunks
                const __nv_bfloat16* srcb = (u < 1536) ? Bhi : Blo;
                const int v = u & 511;
                const int row = v >> 4, c = v & 15;
                const int gn = nBase + c * 8;
                const bool ok = gn < Ntot;
                const void* src = srcb + (size_t)(kb + row) * Ntot + (ok ? gn : 0);
                uint32_t dst = base + 2 * A_TILE_B + ((u < 1536) ? 0 : B_TILE_B)
                             + row * 272 + c * 16;
                cp16(dst, src, ok);
            }
        }
    };

    // per-thread fragment address offsets
    // A: rows (warpM*64 + lane%16), 16B column chunk = (lane/16)
    const uint32_t aoff = ((warpM << 6) + (lane & 15)) * 80 + (lane >> 4) * 16;
    // B: k-row (lane%16) x 272B stride, warp column offset = warpN*32 cols*2B
    const uint32_t boff = (lane & 15) * 272 + (warpN << 6);

    auto compute = [&](int buf) {
        const uint32_t base = sb + buf * BUF_B;
        const uint32_t aHi = base;
        const uint32_t aLo = base + A_TILE_B;
        const uint32_t bHi = base + 2 * A_TILE_B;
        const uint32_t bLo = bHi + B_TILE_B;
#pragma unroll
        for (int k16 = 0; k16 < 2; ++k16) {
            uint32_t aF[4][4], bF[4][2];
            // Ahi fragments
#pragma unroll
            for (int mi = 0; mi < 4; ++mi)
                ldsm_x4(aF[mi], aHi + aoff + mi * (16 * 80) + k16 * 32);
            // Blo fragments -> Ahi*Blo
#pragma unroll
            for (int ni = 0; ni < 4; ++ni)
                ldsm_x2t(bF[ni], bLo + boff + ni * 16 + k16 * (16 * 272));
#pragma unroll
            for (int mi = 0; mi < 4; ++mi)
#pragma unroll
                for (int ni = 0; ni < 4; ++ni)
                    mma16816(acc[mi][ni], aF[mi], bF[ni]);
            // Bhi fragments -> Ahi*Bhi
#pragma unroll
            for (int ni = 0; ni < 4; ++ni)
                ldsm_x2t(bF[ni], bHi + boff + ni * 16 + k16 * (16 * 272));
#pragma unroll
            for (int mi = 0; mi < 4; ++mi)
#pragma unroll
                for (int ni = 0; ni < 4; ++ni)
                    mma16816(acc[mi][ni], aF[mi], bF[ni]);
            // Alo fragments -> Alo*Bhi
#pragma unroll
            for (int mi = 0; mi < 4; ++mi)
                ldsm_x4(aF[mi], aLo + aoff + mi * (16 * 80) + k16 * 32);
#pragma unroll
            for (int mi = 0; mi < 4; ++mi)
#pragma unroll
                for (int ni = 0; ni < 4; ++ni)
                    mma16816(acc[mi][ni], aF[mi], bF[ni]);
        }
    };

    // ---- mainloop (double buffered) ----
    load_tiles(0, 0);
    CP_COMMIT();
    for (int it = 0; it < iters; ++it) {
        if (it + 1 < iters) load_tiles((it + 1) & 1, it + 1);
        CP_COMMIT();
        CP_WAIT1();
        __syncthreads();
        compute(it & 1);
        __syncthreads();
    }

    // ---- epilogue ----
#pragma unroll
    for (int mi = 0; mi < 4; ++mi) {
        const int r0 = mBase + (warpM << 6) + mi * 16 + (lane >> 2);
#pragma unroll
        for (int ni = 0; ni < 4; ++ni) {
            const int c0 = nBase + (warpN << 5) + ni * 8 + ((lane & 3) << 1);
            const float* a = acc[mi][ni];
#pragma unroll
            for (int half = 0; half < 2; ++half) {
                const int row = r0 + half * 8;
                if (row >= M || c0 >= Ntot) continue;
                const float v0 = a[half * 2 + 0];
                const float v1 = a[half * 2 + 1];
                if (S == 1) {
                    const float bv = bias[row];
                    int bb = c0 / HW;
                    int hw = c0 - bb * HW;
                    float* o = C + ((size_t)bb * COUT + row) * HW + hw;
                    o[0] = v0 + bv;
                    o[1] = v1 + bv;   // c0 even, HW even -> same image row
                } else {
                    float* P = C + (size_t)blockIdx.z * M * Ntot
                             + (size_t)row * Ntot + c0;
                    P[0] = v0;
                    P[1] = v1;
                }
            }
        }
    }
}

// ---------------------------------------------------------------------------
// split-K reduces (deterministic; bias/sigmoid/NCHW fused)
// ---------------------------------------------------------------------------
__global__ void reduce_off_kernel(const float* __restrict__ P,
                                  const float* __restrict__ ob,
                                  float* __restrict__ off, int N, int S)
{
    int idx = blockIdx.x * blockDim.x + threadIdx.x;
    if (idx >= 27 * N) return;
    int r = idx / N;
    float v = ob[r];
    for (int s = 0; s < S; ++s)
        v += P[(size_t)s * 27 * N + idx];
    if (r >= 18)
        v = 1.f / (1.f + expf(-v));
    off[idx] = v;
}

__global__ void reduce_main_kernel(const float* __restrict__ P,
                                   const float* __restrict__ bias,
                                   float* __restrict__ out, int N, int HW, int S)
{
    int idx = blockIdx.x * blockDim.x + threadIdx.x;
    if (idx >= COUT * N) return;
    int row = idx / N;
    int col = idx - row * N;
    float v = bias[row];
    for (int s = 0; s < S; ++s)
        v += P[(size_t)s * COUT * N + idx];
    int bb = col / HW;
    int hw = col - bb * HW;
    out[((size_t)bb * COUT + row) * HW + hw] = v;
}

// ---------------------------------------------------------------------------
// Host side
// ---------------------------------------------------------------------------
extern "C" void kernel_launch(void* const* d_in, const int* in_sizes, int n_in,
                              void* d_out, int out_size)
{
    const float* xs[4]  = {nullptr, nullptr, nullptr, nullptr};
    const float* ws[4]  = {nullptr, nullptr, nullptr, nullptr};
    const float* bs[4]  = {nullptr, nullptr, nullptr, nullptr};
    const float* ows[3] = {nullptr, nullptr, nullptr};
    const float* obs[3] = {nullptr, nullptr, nullptr};
    int wi = 0, bi = 0, owi = 0, obi = 0;
    for (int i = 0; i < n_in; ++i) {
        const float* p = (const float*)d_in[i];
        switch (in_sizes[i]) {
            case 2 * 256 * 96 * 96: xs[0] = p; break;
            case 2 * 256 * 48 * 48: xs[1] = p; break;
            case 2 * 256 * 24 * 24: xs[2] = p; break;
            case 2 * 256 * 12 * 12: xs[3] = p; break;
            case 256 * 256 * 3 * 3: if (wi  < 4) ws[wi++]   = p; break;
            case 256:               if (bi  < 4) bs[bi++]   = p; break;
            case 27 * 256 * 3 * 3:  if (owi < 3) ows[owi++] = p; break;
            case 27:                if (obi < 3) obs[obi++] = p; break;
            default: break;
        }
    }

    float* out = (float*)d_out;
    float* s;    cudaGetSymbolAddress((void**)&s,    g_s);
    float* off;  cudaGetSymbolAddress((void**)&off,  g_off);
    float* part; cudaGetSymbolAddress((void**)&part, g_part);
    __nv_bfloat16* chi;  cudaGetSymbolAddress((void**)&chi,  g_colshi);
    __nv_bfloat16* clo;  cudaGetSymbolAddress((void**)&clo,  g_colslo);
    __nv_bfloat16* whi;  cudaGetSymbolAddress((void**)&whi,  g_whi);
    __nv_bfloat16* wlo;  cudaGetSymbolAddress((void**)&wlo,  g_wlo);
    __nv_bfloat16* owhi; cudaGetSymbolAddress((void**)&owhi, g_owhi);
    __nv_bfloat16* owlo; cudaGetSymbolAddress((void**)&owlo, g_owlo);

    cudaFuncSetAttribute(gemm_kernel,
                         cudaFuncAttributeMaxDynamicSharedMemorySize, GEMM_SMEM);

    const size_t OFF0 = 0;
    const size_t OFF1 = OFF0 + (size_t)2 * 256 * 96 * 96;
    const size_t OFF2 = OFF1 + (size_t)2 * 256 * 48 * 48;
    const size_t OFF3 = OFF2 + (size_t)2 * 256 * 24 * 24;
    const size_t outOff[4] = {OFF0, OFF1, OFF2, OFF3};

    // weight splits (cheap, deterministic, every call)
    for (int i = 0; i < 4; ++i)
        wsplit_kernel<<<(256 * KK + 255) / 256, 256>>>(
            ws[i], whi + (size_t)i * 256 * KK, wlo + (size_t)i * 256 * KK,
            256 * KK);
    for (int j = 0; j < 3; ++j)
        wsplit_kernel<<<(27 * KK + 255) / 256, 256>>>(
            ows[j], owhi + (size_t)j * 27 * KK, owlo + (size_t)j * 27 * KK,
            27 * KK);

    const int Hs[4]    = {96, 48, 24, 12};
    const int mainS[4] = {1, 3, 12, 36};   // divisors of 72; part fits 5M floats
    const int offS[4]  = {1, 6, 24, 72};

    // ---- levels 3, 2, 1: modulated deformable conv ----
    for (int lvl = 3; lvl >= 1; --lvl) {
        int H = Hs[lvl], W = H;
        int HW = H * W;
        int N = 2 * HW;

        const float* sin;
        if (lvl == 3) {
            sin = xs[3];
        } else {
            int total = 2 * CIN * HW;
            addup_kernel<<<(total + 255) / 256, 256>>>(
                xs[lvl], out + outOff[lvl + 1], s, H, W);
            sin = s;
        }

        // offset conv: im2col(bf16) -> GEMM(splitK) -> reduce(+sigmoid)
        im2col_kernel<<<(CIN * N + 255) / 256, 256>>>(sin, chi, clo, H, W, N);
        {
            int S = offS[lvl];
            dim3 grid((N + 127) / 128, 1, S);
            gemm_kernel<<<grid, 256, GEMM_SMEM>>>(
                owhi + (size_t)(lvl - 1) * 27 * KK,
                owlo + (size_t)(lvl - 1) * 27 * KK,
                chi, clo, obs[lvl - 1], part, 27, N, HW, S);
            reduce_off_kernel<<<(27 * N + 255) / 256, 256>>>(
                part, obs[lvl - 1], off, N, S);
        }

        // main conv: dcols(bf16) -> GEMM(splitK) -> reduce(NCHW)
        dcols_kernel<<<(CIN * N + 255) / 256, 256>>>(sin, off, chi, clo, H, W, N);
        {
            int S = mainS[lvl];
            dim3 grid((N + 127) / 128, 2, S);
            gemm_kernel<<<grid, 256, GEMM_SMEM>>>(
                whi + (size_t)lvl * 256 * KK, wlo + (size_t)lvl * 256 * KK,
                chi, clo, bs[lvl], part, COUT, N, HW, S);
            reduce_main_kernel<<<(COUT * N + 255) / 256, 256>>>(
                part, bs[lvl], out + outOff[lvl], N, HW, S);
        }
    }

    // ---- level 0: plain conv, fused epilogue (288 CTAs, S=1) ----
    {
        int H = 96, W = 96, HW = H * W, N = 2 * HW;
        int total = 2 * CIN * HW;
        addup_kernel<<<(total + 255) / 256, 256>>>(xs[0], out + OFF1, s, H, W);
        im2col_kernel<<<(CIN * N + 255) / 256, 256>>>(s, chi, clo, H, W, N);
        dim3 grid((N + 127) / 128, 2, 1);
        gemm_kernel<<<grid, 256, GEMM_SMEM>>>(
            whi, wlo, chi, clo, bs[0], out + OFF0, COUT, N, HW, 1);
    }
}